// round 4
// baseline (speedup 1.0000x reference)
#include <cuda_runtime.h>
#include <cstdint>

#define B_    2
#define S_    2048
#define HID_  4096
#define NH_   32
#define NKV_  8
#define HD_   128

// ---------------------------------------------------------------------------
// Scratch (static __device__ arrays; no allocation allowed in kernel_launch)
// ---------------------------------------------------------------------------
__device__ float g_Q[(size_t)B_ * NH_ * S_ * HD_];    // 16.8M floats
__device__ float g_K[(size_t)B_ * NKV_ * S_ * HD_];   //  4.2M floats
__device__ float g_V[(size_t)B_ * NKV_ * S_ * HD_];   //  4.2M floats
__device__ float g_ctx[(size_t)B_ * S_ * HID_];       // 16.8M floats

// ---------------------------------------------------------------------------
// NT SGEMM: C[m,n] = sum_k A[m,k] * W[n,k]   (A: MxK row-major, W: NxK row-major)
// 128x128 block tile, BK=16, 256 threads, 8x8 per-thread micro-tile with
// split-4 fragments (rows ty*4 and 64+ty*4) for conflict-free LDS.128.
// Register-prefetch double buffering hides global latency under compute.
// MODE 0: scatter C into g_Q layout [b, h, s, d]
// MODE 1: scatter C into g_K / g_V layouts [b, kvh, s, d]
// MODE 2: C = A(=g_ctx) @ Wd^T + bias  -> out, row-major [m, n]
// ---------------------------------------------------------------------------
template <int MODE>
__global__ __launch_bounds__(256)
void gemm_nt(const float* __restrict__ A, const float* __restrict__ W,
             const float* __restrict__ bias, float* __restrict__ out)
{
    const int K = HID_;
    __shared__ __align__(16) float sA[16][128];
    __shared__ __align__(16) float sB[16][128];

    const int tid = threadIdx.x;
    const int bm = blockIdx.y, bn = blockIdx.x;
    const float* Ap = (MODE == 2) ? g_ctx : A;

    const int lrow = tid >> 2;          // 0..63
    const int lk4  = (tid & 3) * 4;     // 0,4,8,12

    const float* a0p = Ap + (size_t)(bm * 128 + lrow) * K + lk4;
    const float* a1p = a0p + (size_t)64 * K;
    const float* b0p = W  + (size_t)(bn * 128 + lrow) * K + lk4;
    const float* b1p = b0p + (size_t)64 * K;

    float acc[8][8];
#pragma unroll
    for (int i = 0; i < 8; i++)
#pragma unroll
        for (int j = 0; j < 8; j++) acc[i][j] = 0.f;

    // initial tile load
    float4 ra0 = *(const float4*)a0p;
    float4 ra1 = *(const float4*)a1p;
    float4 rb0 = *(const float4*)b0p;
    float4 rb1 = *(const float4*)b1p;
    sA[lk4 + 0][lrow] = ra0.x; sA[lk4 + 1][lrow] = ra0.y;
    sA[lk4 + 2][lrow] = ra0.z; sA[lk4 + 3][lrow] = ra0.w;
    sA[lk4 + 0][64 + lrow] = ra1.x; sA[lk4 + 1][64 + lrow] = ra1.y;
    sA[lk4 + 2][64 + lrow] = ra1.z; sA[lk4 + 3][64 + lrow] = ra1.w;
    sB[lk4 + 0][lrow] = rb0.x; sB[lk4 + 1][lrow] = rb0.y;
    sB[lk4 + 2][lrow] = rb0.z; sB[lk4 + 3][lrow] = rb0.w;
    sB[lk4 + 0][64 + lrow] = rb1.x; sB[lk4 + 1][64 + lrow] = rb1.y;
    sB[lk4 + 2][64 + lrow] = rb1.z; sB[lk4 + 3][64 + lrow] = rb1.w;
    __syncthreads();

    const int ty = tid >> 4, tx = tid & 15;
    const int nk = K / 16;

    for (int kt = 0; kt < nk; kt++) {
        if (kt + 1 < nk) {
            const int off = (kt + 1) * 16;
            ra0 = *(const float4*)(a0p + off);
            ra1 = *(const float4*)(a1p + off);
            rb0 = *(const float4*)(b0p + off);
            rb1 = *(const float4*)(b1p + off);
        }
#pragma unroll
        for (int k = 0; k < 16; k++) {
            float4 x0 = *(const float4*)&sA[k][ty * 4];
            float4 x1 = *(const float4*)&sA[k][64 + ty * 4];
            float4 y0 = *(const float4*)&sB[k][tx * 4];
            float4 y1 = *(const float4*)&sB[k][64 + tx * 4];
            float av[8] = {x0.x, x0.y, x0.z, x0.w, x1.x, x1.y, x1.z, x1.w};
            float bv[8] = {y0.x, y0.y, y0.z, y0.w, y1.x, y1.y, y1.z, y1.w};
#pragma unroll
            for (int i = 0; i < 8; i++)
#pragma unroll
                for (int j = 0; j < 8; j++)
                    acc[i][j] = fmaf(av[i], bv[j], acc[i][j]);
        }
        __syncthreads();
        if (kt + 1 < nk) {
            sA[lk4 + 0][lrow] = ra0.x; sA[lk4 + 1][lrow] = ra0.y;
            sA[lk4 + 2][lrow] = ra0.z; sA[lk4 + 3][lrow] = ra0.w;
            sA[lk4 + 0][64 + lrow] = ra1.x; sA[lk4 + 1][64 + lrow] = ra1.y;
            sA[lk4 + 2][64 + lrow] = ra1.z; sA[lk4 + 3][64 + lrow] = ra1.w;
            sB[lk4 + 0][lrow] = rb0.x; sB[lk4 + 1][lrow] = rb0.y;
            sB[lk4 + 2][lrow] = rb0.z; sB[lk4 + 3][lrow] = rb0.w;
            sB[lk4 + 0][64 + lrow] = rb1.x; sB[lk4 + 1][64 + lrow] = rb1.y;
            sB[lk4 + 2][64 + lrow] = rb1.z; sB[lk4 + 3][64 + lrow] = rb1.w;
            __syncthreads();
        }
    }

    // epilogue
    const int mB = bm * 128, nB = bn * 128;
#pragma unroll
    for (int i = 0; i < 8; i++) {
        const int lm = (i < 4) ? (ty * 4 + i) : (64 + ty * 4 + (i - 4));
        const int m = mB + lm;
        const int bb = m >> 11;          // / S_
        const int s = m & (S_ - 1);
#pragma unroll
        for (int j = 0; j < 8; j++) {
            const int ln = (j < 4) ? (tx * 4 + j) : (64 + tx * 4 + (j - 4));
            const int n = nB + ln;
            const float v = acc[i][j];
            if (MODE == 0) {
                const int h = n >> 7, d = n & 127;
                g_Q[(((size_t)bb * NH_ + h) * S_ + s) * HD_ + d] = v;
            } else if (MODE == 1) {
                const int kvh = n >> 8, jj = n & 255;
                if (jj < 128)
                    g_K[(((size_t)bb * NKV_ + kvh) * S_ + s) * HD_ + jj] = v;
                else
                    g_V[(((size_t)bb * NKV_ + kvh) * S_ + s) * HD_ + (jj - 128)] = v;
            } else {
                out[(size_t)m * HID_ + n] = v + bias[n];
            }
        }
    }
}

// ---------------------------------------------------------------------------
// RoPE applied in place to g_Q and g_K. One thread per (row, d<64) pair.
// emb = concat(freqs, freqs) -> cos/sin identical for d and d+64.
// ---------------------------------------------------------------------------
__global__ void rope_kernel(const float* __restrict__ cosT,
                            const float* __restrict__ sinT)
{
    const int qPairs = B_ * NH_ * S_ * (HD_ / 2);          // 2^23
    const int tPairs = qPairs + B_ * NKV_ * S_ * (HD_ / 2);
    int idx = blockIdx.x * blockDim.x + threadIdx.x;
    if (idx >= tPairs) return;
    float* base;
    int li;
    if (idx < qPairs) { li = idx; base = g_Q; }
    else              { li = idx - qPairs; base = g_K; }
    const int dp = li & 63;
    const int s = (li >> 6) & (S_ - 1);
    const int bh = li >> 17;                                // (s,dp) span 2^17
    const float c = cosT[s * HD_ + dp];
    const float sn = sinT[s * HD_ + dp];
    float* p = base + ((size_t)bh * S_ + s) * HD_;
    const float x1 = p[dp], x2 = p[dp + 64];
    p[dp]      = x1 * c - x2 * sn;
    p[dp + 64] = x2 * c + x1 * sn;
}

// ---------------------------------------------------------------------------
// Causal flash attention, fp32. One block = (b, h, 64-row q tile).
// smem: Q^T [128][68], K^T [128][68], V [64][128], P^T [64][68]  (~117 KB)
// 256 threads as 16x16; S micro-tile 4x4; O micro-tile 4 rows x (4+4) cols.
// Online softmax state per row replicated across the 16 tx lanes (shfl w=16).
// ---------------------------------------------------------------------------
#define ATTN_SMEM_FLOATS (128 * 68 * 2 + 64 * 128 + 64 * 68)
#define ATTN_SMEM_BYTES  (ATTN_SMEM_FLOATS * 4)

__global__ __launch_bounds__(256)
void attn_kernel()
{
    extern __shared__ float sm[];
    float* sQt = sm;                       // [128][68]
    float* sKt = sm + 128 * 68;            // [128][68]
    float* sV  = sKt + 128 * 68;           // [64][128]
    float* sPt = sV + 64 * 128;            // [64][68]

    const int qt = blockIdx.x;             // 0..31
    const int h  = blockIdx.y;             // 0..31
    const int b  = blockIdx.z;             // 0..1
    const int kvh = h >> 2;                // GQA: 4 q heads per kv head
    const int tid = threadIdx.x;
    const int ty = tid >> 4, tx = tid & 15;

    const float* Qg = g_Q + (((size_t)b * NH_ + h) * S_ + qt * 64) * HD_;
    const float* Kb = g_K + ((size_t)b * NKV_ + kvh) * S_ * HD_;
    const float* Vb = g_V + ((size_t)b * NKV_ + kvh) * S_ * HD_;

    // load Q tile transposed
#pragma unroll
    for (int it = 0; it < 8; it++) {
        const int f = tid + it * 256;      // 0..2047 float4s
        const int r = f >> 5;              // row 0..63
        const int d4 = (f & 31) * 4;
        const float4 v = *(const float4*)(Qg + (size_t)r * HD_ + d4);
        sQt[(d4 + 0) * 68 + r] = v.x;
        sQt[(d4 + 1) * 68 + r] = v.y;
        sQt[(d4 + 2) * 68 + r] = v.z;
        sQt[(d4 + 3) * 68 + r] = v.w;
    }

    float mi[4], li[4], O[4][8];
#pragma unroll
    for (int i = 0; i < 4; i++) {
        mi[i] = -1e30f; li[i] = 0.f;
#pragma unroll
        for (int j = 0; j < 8; j++) O[i][j] = 0.f;
    }

    const float scale = 0.08838834764831845f;   // 1/sqrt(128)
    const int nkt = qt + 1;                     // causal: only lower tiles

    for (int kt = 0; kt < nkt; kt++) {
        __syncthreads();   // prior PV reads (and Q store on iter 0) complete
        const float* Kg = Kb + (size_t)kt * 64 * HD_;
        const float* Vg = Vb + (size_t)kt * 64 * HD_;
#pragma unroll
        for (int it = 0; it < 8; it++) {
            const int f = tid + it * 256;
            const int r = f >> 5;
            const int d4 = (f & 31) * 4;
            const float4 kv = *(const float4*)(Kg + (size_t)r * HD_ + d4);
            sKt[(d4 + 0) * 68 + r] = kv.x;
            sKt[(d4 + 1) * 68 + r] = kv.y;
            sKt[(d4 + 2) * 68 + r] = kv.z;
            sKt[(d4 + 3) * 68 + r] = kv.w;
            *(float4*)&sV[r * 128 + d4] = *(const float4*)(Vg + (size_t)r * HD_ + d4);
        }
        __syncthreads();

        // S = Q K^T  (4x4 micro-tile per thread)
        float sacc[4][4];
#pragma unroll
        for (int i = 0; i < 4; i++)
#pragma unroll
            for (int j = 0; j < 4; j++) sacc[i][j] = 0.f;

#pragma unroll 8
        for (int d = 0; d < 128; d++) {
            const float4 a = *(const float4*)&sQt[d * 68 + ty * 4];
            const float4 kk = *(const float4*)&sKt[d * 68 + tx * 4];
            const float av[4] = {a.x, a.y, a.z, a.w};
            const float kv2[4] = {kk.x, kk.y, kk.z, kk.w};
#pragma unroll
            for (int i = 0; i < 4; i++)
#pragma unroll
                for (int j = 0; j < 4; j++)
                    sacc[i][j] = fmaf(av[i], kv2[j], sacc[i][j]);
        }

        // mask + online softmax
        const int rq0 = qt * 64 + ty * 4;
        const int ck0 = kt * 64 + tx * 4;
        float corr[4];
#pragma unroll
        for (int i = 0; i < 4; i++) {
            float sv[4];
#pragma unroll
            for (int j = 0; j < 4; j++)
                sv[j] = (ck0 + j <= rq0 + i) ? sacc[i][j] * scale : -1e30f;
            float rm = fmaxf(fmaxf(sv[0], sv[1]), fmaxf(sv[2], sv[3]));
#pragma unroll
            for (int msk = 8; msk; msk >>= 1)
                rm = fmaxf(rm, __shfl_xor_sync(0xffffffffu, rm, msk, 16));
            const float newm = fmaxf(mi[i], rm);
            corr[i] = __expf(mi[i] - newm);
            float rs = 0.f;
#pragma unroll
            for (int j = 0; j < 4; j++) {
                const float pz = __expf(sv[j] - newm);
                rs += pz;
                sPt[(tx * 4 + j) * 68 + ty * 4 + i] = pz;
            }
#pragma unroll
            for (int msk = 8; msk; msk >>= 1)
                rs += __shfl_xor_sync(0xffffffffu, rs, msk, 16);
            li[i] = li[i] * corr[i] + rs;
            mi[i] = newm;
        }
        __syncthreads();   // P visible to all

        // O = O*corr + P V
#pragma unroll
        for (int i = 0; i < 4; i++)
#pragma unroll
            for (int j = 0; j < 8; j++) O[i][j] *= corr[i];

#pragma unroll 4
        for (int c = 0; c < 64; c++) {
            const float4 p = *(const float4*)&sPt[c * 68 + ty * 4];
            const float4 v0 = *(const float4*)&sV[c * 128 + tx * 4];
            const float4 v1 = *(const float4*)&sV[c * 128 + 64 + tx * 4];
            const float pv[4] = {p.x, p.y, p.z, p.w};
            const float va[8] = {v0.x, v0.y, v0.z, v0.w, v1.x, v1.y, v1.z, v1.w};
#pragma unroll
            for (int i = 0; i < 4; i++)
#pragma unroll
                for (int j = 0; j < 8; j++)
                    O[i][j] = fmaf(pv[i], va[j], O[i][j]);
        }
    }

    // normalize + write to context in [b, s, hid] layout
#pragma unroll
    for (int i = 0; i < 4; i++) {
        const float inv = 1.f / li[i];
        const int srow = qt * 64 + ty * 4 + i;
        float* dst = g_ctx + ((size_t)b * S_ + srow) * HID_ + h * HD_;
#pragma unroll
        for (int j = 0; j < 4; j++) dst[tx * 4 + j] = O[i][j] * inv;
#pragma unroll
        for (int j = 0; j < 4; j++) dst[64 + tx * 4 + j] = O[i][j + 4] * inv;
    }
}

// ---------------------------------------------------------------------------
// Inputs (metadata order): hidden_states, attention_mask, cos, sin,
//                          Wq, Wkv, Wd, bd
// attention_mask is exactly causal -> enforced analytically, input unused.
// ---------------------------------------------------------------------------
extern "C" void kernel_launch(void* const* d_in, const int* in_sizes, int n_in,
                              void* d_out, int out_size)
{
    (void)in_sizes; (void)n_in; (void)out_size;
    const float* hidden = (const float*)d_in[0];
    const float* cosT   = (const float*)d_in[2];
    const float* sinT   = (const float*)d_in[3];
    const float* Wq     = (const float*)d_in[4];
    const float* Wkv    = (const float*)d_in[5];
    const float* Wd     = (const float*)d_in[6];
    const float* bd     = (const float*)d_in[7];
    float* out = (float*)d_out;

    cudaFuncSetAttribute(attn_kernel,
                         cudaFuncAttributeMaxDynamicSharedMemorySize,
                         ATTN_SMEM_BYTES);

    const int M = B_ * S_;                     // 4096
    gemm_nt<0><<<dim3(HID_ / 128, M / 128), 256>>>(hidden, Wq, nullptr, nullptr);
    gemm_nt<1><<<dim3((2 * NKV_ * HD_) / 128, M / 128), 256>>>(hidden, Wkv, nullptr, nullptr);

    const int totalPairs = B_ * NH_ * S_ * (HD_ / 2) + B_ * NKV_ * S_ * (HD_ / 2);
    rope_kernel<<<(totalPairs + 255) / 256, 256>>>(cosT, sinT);

    attn_kernel<<<dim3(S_ / 64, NH_, B_), 256, ATTN_SMEM_BYTES>>>();

    gemm_nt<2><<<dim3(HID_ / 128, M / 128), 256>>>(nullptr, Wd, bd, out);
}